// round 2
// baseline (speedup 1.0000x reference)
#include <cuda_runtime.h>

// Problem constants
#define IMGS   128      // BS*T
#define CH     256      // z channels
#define EMB    256
#define HW     256      // H*W
#define NPIX   32768    // IMGS*HW
#define VOCAB  4096

// Output region offsets (elements) in d_out:
//   z:      [0,        8388608)
//   zq:     [8388608, 16777216)
//   recon:  [16777216, 25165824)
//   tokens: [25165824, 25198592)

__device__ unsigned long long g_packed[NPIX];
__device__ float g_csq[VOCAB];
__device__ float g_zsq[NPIX];
__device__ int   g_tok[NPIX];

__device__ __forceinline__ unsigned int f2ord(float f) {
    unsigned int u = __float_as_uint(f);
    return (u & 0x80000000u) ? ~u : (u | 0x80000000u);
}

// ---------------------------------------------------------------------------
// Init: codebook squared norms (one warp per row) + packed argmin buffer reset
// ---------------------------------------------------------------------------
__global__ void k_init(const float* __restrict__ cb) {
    int t = threadIdx.x;
    int gt = blockIdx.x * 128 + t;
    if (gt < NPIX) g_packed[gt] = ~0ull;

    int r = blockIdx.x * 4 + (t >> 5);   // 1024 blocks * 4 warps = 4096 rows
    int lane = t & 31;
    if (r < VOCAB) {
        const float* row = cb + r * EMB;
        float s = 0.f;
        #pragma unroll 4
        for (int e = lane; e < EMB; e += 32) { float v = row[e]; s += v * v; }
        #pragma unroll
        for (int o = 16; o; o >>= 1) s += __shfl_down_sync(0xFFFFFFFFu, s, o);
        if (lane == 0) g_csq[r] = s;
    }
}

// ---------------------------------------------------------------------------
// 256x256x256 per-image GEMM: Out[m,n] = sum_k W[m,k]*xf(In[k,n]) + bias[m]
// XFORM: input transform 2x-1 (pre-quantize path)
// Block: 64x64 tile, 256 threads, 4x4 microtile, K-chunk 16
// ---------------------------------------------------------------------------
template<bool XFORM>
__global__ void __launch_bounds__(256) k_gemm256(
    const float* __restrict__ W, const float* __restrict__ bias,
    const float* __restrict__ In, float* __restrict__ Out)
{
    __shared__ float Ws[16][68];   // [k][m], padded
    __shared__ float Bs[16][64];   // [k][n]
    const int img = blockIdx.z;
    const int m0 = blockIdx.y * 64, n0 = blockIdx.x * 64;
    const float* in = In + (size_t)img * 65536;
    float* out = Out + (size_t)img * 65536;
    const int t = threadIdx.x;
    const int ty = t >> 4, tx = t & 15;

    float acc[4][4] = {};

    for (int k0 = 0; k0 < 256; k0 += 16) {
        {   // W tile 64 rows x 16 k
            int row = t >> 2;
            int c4  = (t & 3) * 4;
            float4 w4 = *reinterpret_cast<const float4*>(&W[(m0 + row) * 256 + k0 + c4]);
            Ws[c4 + 0][row] = w4.x; Ws[c4 + 1][row] = w4.y;
            Ws[c4 + 2][row] = w4.z; Ws[c4 + 3][row] = w4.w;
        }
        {   // B tile 16 k x 64 n
            int kk = t >> 4;
            int n4 = (t & 15) * 4;
            float4 b4 = *reinterpret_cast<const float4*>(&in[(k0 + kk) * 256 + n0 + n4]);
            if (XFORM) {
                b4.x = 2.f * b4.x - 1.f; b4.y = 2.f * b4.y - 1.f;
                b4.z = 2.f * b4.z - 1.f; b4.w = 2.f * b4.w - 1.f;
            }
            *reinterpret_cast<float4*>(&Bs[kk][n4]) = b4;
        }
        __syncthreads();
        #pragma unroll
        for (int kk = 0; kk < 16; kk++) {
            float a[4], b[4];
            *reinterpret_cast<float4*>(a) = *reinterpret_cast<float4*>(&Ws[kk][ty * 4]);
            *reinterpret_cast<float4*>(b) = *reinterpret_cast<float4*>(&Bs[kk][tx * 4]);
            #pragma unroll
            for (int i = 0; i < 4; i++)
                #pragma unroll
                for (int j = 0; j < 4; j++)
                    acc[i][j] += a[i] * b[j];
        }
        __syncthreads();
    }

    #pragma unroll
    for (int i = 0; i < 4; i++) {
        int m = m0 + ty * 4 + i;
        float bm = bias[m];
        float4 o;
        o.x = acc[i][0] + bm; o.y = acc[i][1] + bm;
        o.z = acc[i][2] + bm; o.w = acc[i][3] + bm;
        *reinterpret_cast<float4*>(&out[m * 256 + n0 + tx * 4]) = o;
    }
}

// ---------------------------------------------------------------------------
// z squared norms per pixel (deterministic sequential sum over e)
// ---------------------------------------------------------------------------
__global__ void k_zsq(const float* __restrict__ z) {
    int img = blockIdx.x;
    int hw = threadIdx.x;
    const float* p = z + (size_t)img * 65536 + hw;
    float s = 0.f;
    #pragma unroll 8
    for (int e = 0; e < 256; e++) { float v = p[e * 256]; s += v * v; }
    g_zsq[img * 256 + hw] = s;
}

// ---------------------------------------------------------------------------
// Distance GEMM + fused argmin: D[v,n] = (zsq[n]+csq[v]) - 2*dot(C[v],Z[:,n])
// Block: 128(v) x 128(n), 256 threads, 8x8 microtile, K-chunk 8.
// Min reduced via packed (ordered-dist<<32 | idx) -> shared -> global atomicMin.
// ---------------------------------------------------------------------------
__global__ void __launch_bounds__(256) k_dist(
    const float* __restrict__ cb, const float* __restrict__ z)
{
    __shared__ float As[8][132];   // [e][v], padded
    __shared__ float Bs[8][128];   // [e][n]
    __shared__ unsigned long long red[128];

    const int v0 = blockIdx.y * 128;
    const int n0 = blockIdx.x * 128;
    // pixel n = img*256 + hw ; z stored [img][e][hw] ; tile lives in one image
    const float* zb = z + (size_t)(n0 >> 8) * 65536 + (n0 & 255);
    const int t = threadIdx.x;
    const int ty = t >> 4, tx = t & 15;

    if (t < 128) red[t] = ~0ull;

    float acc[8][8] = {};

    for (int e0 = 0; e0 < 256; e0 += 8) {
        {   // codebook tile: 128 v x 8 e
            int v = t >> 1;
            int e4 = (t & 1) * 4;
            float4 a4 = *reinterpret_cast<const float4*>(&cb[(v0 + v) * 256 + e0 + e4]);
            As[e4 + 0][v] = a4.x; As[e4 + 1][v] = a4.y;
            As[e4 + 2][v] = a4.z; As[e4 + 3][v] = a4.w;
        }
        {   // z tile: 8 e x 128 n
            int e = t >> 5;
            int n4 = (t & 31) * 4;
            float4 b4 = *reinterpret_cast<const float4*>(&zb[(e0 + e) * 256 + n4]);
            *reinterpret_cast<float4*>(&Bs[e][n4]) = b4;
        }
        __syncthreads();
        #pragma unroll
        for (int k = 0; k < 8; k++) {
            float a[8], b[8];
            *reinterpret_cast<float4*>(a)     = *reinterpret_cast<float4*>(&As[k][ty * 8]);
            *reinterpret_cast<float4*>(a + 4) = *reinterpret_cast<float4*>(&As[k][ty * 8 + 4]);
            *reinterpret_cast<float4*>(b)     = *reinterpret_cast<float4*>(&Bs[k][tx * 8]);
            *reinterpret_cast<float4*>(b + 4) = *reinterpret_cast<float4*>(&Bs[k][tx * 8 + 4]);
            #pragma unroll
            for (int i = 0; i < 8; i++)
                #pragma unroll
                for (int j = 0; j < 8; j++)
                    acc[i][j] += a[i] * b[j];
        }
        __syncthreads();
    }

    float csq[8];
    #pragma unroll
    for (int i = 0; i < 8; i++) csq[i] = g_csq[v0 + ty * 8 + i];

    #pragma unroll
    for (int j = 0; j < 8; j++) {
        int n = n0 + tx * 8 + j;
        float zs = g_zsq[n];
        unsigned long long best = ~0ull;
        #pragma unroll
        for (int i = 0; i < 8; i++) {
            // exact replication of ref: fl(fl(zs+csq) - fl(2*dot)); *2 exact
            float d = (zs + csq[i]) - 2.0f * acc[i][j];
            unsigned long long key =
                ((unsigned long long)f2ord(d) << 32) | (unsigned int)(v0 + ty * 8 + i);
            best = key < best ? key : best;
        }
        atomicMin(&red[tx * 8 + j], best);
    }
    __syncthreads();
    if (t < 128) atomicMin(&g_packed[n0 + t], red[t]);
}

// ---------------------------------------------------------------------------
// Extract tokens (and write token output as float)
// ---------------------------------------------------------------------------
__global__ void k_tokens(float* __restrict__ tok_out) {
    int n = blockIdx.x * 256 + threadIdx.x;
    int tok = (int)(g_packed[n] & 0xFFFFFFFFull);
    g_tok[n] = tok;
    tok_out[n] = (float)tok;
}

// ---------------------------------------------------------------------------
// Gather zq = codebook[token] into [img][e][hw] layout (coalesced writes)
// ---------------------------------------------------------------------------
__global__ void k_zq(const float* __restrict__ cb, float* __restrict__ zq) {
    unsigned int g = blockIdx.x * 256 + threadIdx.x;   // < 8388608
    int hw  = g & 255;
    int e   = (g >> 8) & 255;
    int img = g >> 16;
    int n = img * 256 + hw;
    zq[g] = cb[g_tok[n] * 256 + e];
}

// ---------------------------------------------------------------------------
extern "C" void kernel_launch(void* const* d_in, const int* in_sizes, int n_in,
                              void* d_out, int out_size) {
    const float* x      = (const float*)d_in[0];
    const float* cb     = (const float*)d_in[1];
    const float* pre_w  = (const float*)d_in[2];
    const float* pre_b  = (const float*)d_in[3];
    const float* post_w = (const float*)d_in[4];
    const float* post_b = (const float*)d_in[5];

    float* out   = (float*)d_out;
    float* z     = out;
    float* zq    = out + 8388608;
    float* recon = out + 16777216;
    float* toks  = out + 25165824;

    k_init<<<1024, 128>>>(cb);
    k_gemm256<true><<<dim3(4, 4, IMGS), 256>>>(pre_w, pre_b, x, z);
    k_zsq<<<IMGS, 256>>>(z);
    k_dist<<<dim3(NPIX / 128, VOCAB / 128), 256>>>(cb, z);
    k_tokens<<<NPIX / 256, 256>>>(toks);
    k_zq<<<8388608 / 256, 256>>>(cb, zq);
    k_gemm256<false><<<dim3(4, 4, IMGS), 256>>>(post_w, post_b, zq, recon);
}

// round 4
// speedup vs baseline: 1.0181x; 1.0181x over previous
#include <cuda_runtime.h>
#include <cuda_bf16.h>
#include <cstdint>

#define IMGS   128
#define EMB    256
#define NPIX   32768
#define VOCAB  4096

__device__ float g_csq[VOCAB];          // ||c||^2 exact fp32
__device__ float g_csqh[VOCAB];         // csq * 0.5f
__device__ float g_zsq[NPIX];
__device__ int   g_tok[NPIX];
__device__ __nv_bfloat16 g_cbh[VOCAB * EMB];
__device__ unsigned short g_cand[NPIX][16];
__device__ int   g_cnt[NPIX];

__device__ __forceinline__ unsigned int f2ord(float f) {
    unsigned int u = __float_as_uint(f);
    return (u & 0x80000000u) ? ~u : (u | 0x80000000u);
}
__device__ __forceinline__ uint32_t smem_u32(const void* p) {
    uint32_t a;
    asm("{ .reg .u64 t; cvta.to.shared.u64 t, %1; cvt.u32.u64 %0, t; }" : "=r"(a) : "l"(p));
    return a;
}

#define LDM4(r0, r1, r2, r3, addr)                                              \
    asm volatile("ldmatrix.sync.aligned.m8n8.x4.shared.b16 {%0,%1,%2,%3}, [%4];"\
        : "=r"(r0), "=r"(r1), "=r"(r2), "=r"(r3) : "r"(addr))

#define MMA16816(d, a0, a1, a2, a3, b0, b1)                                     \
    asm volatile("mma.sync.aligned.m16n8k16.row.col.f32.bf16.bf16.f32 "         \
        "{%0,%1,%2,%3},{%4,%5,%6,%7},{%8,%9},{%0,%1,%2,%3};"                    \
        : "+f"((d)[0]), "+f"((d)[1]), "+f"((d)[2]), "+f"((d)[3])                \
        : "r"(a0), "r"(a1), "r"(a2), "r"(a3), "r"(b0), "r"(b1))

#define CPA16(dst, src)                                                         \
    asm volatile("cp.async.cg.shared.global [%0], [%1], 16;" :: "r"(dst), "l"(src))
#define CP_COMMIT() asm volatile("cp.async.commit_group;" ::: "memory")

// ---------------------------------------------------------------------------
__global__ void k_init(const float* __restrict__ cb) {
    int t = threadIdx.x;
    int r = blockIdx.x * 4 + (t >> 5);
    int lane = t & 31;
    if (r < VOCAB) {
        const float* row = cb + r * EMB;
        float s = 0.f;
        #pragma unroll 4
        for (int e = lane; e < EMB; e += 32) { float v = row[e]; s += v * v; }
        #pragma unroll
        for (int o = 16; o; o >>= 1) s += __shfl_down_sync(0xFFFFFFFFu, s, o);
        if (lane == 0) { g_csq[r] = s; g_csqh[r] = 0.5f * s; }
    }
}
__global__ void k_cbh(const float* __restrict__ cb) {
    int i = blockIdx.x * 256 + threadIdx.x;
    g_cbh[i] = __float2bfloat16(cb[i]);
}

// ---------------------------------------------------------------------------
// fp32 256x256x256 GEMM (pre/post) — proven in R1
// ---------------------------------------------------------------------------
template<bool XFORM>
__global__ void __launch_bounds__(256) k_gemm256(
    const float* __restrict__ W, const float* __restrict__ bias,
    const float* __restrict__ In, float* __restrict__ Out)
{
    __shared__ float Ws[16][68];
    __shared__ float Bs[16][64];
    const int img = blockIdx.z;
    const int m0 = blockIdx.y * 64, n0 = blockIdx.x * 64;
    const float* in = In + (size_t)img * 65536;
    float* out = Out + (size_t)img * 65536;
    const int t = threadIdx.x;
    const int ty = t >> 4, tx = t & 15;
    float acc[4][4] = {};
    for (int k0 = 0; k0 < 256; k0 += 16) {
        {
            int row = t >> 2, c4 = (t & 3) * 4;
            float4 w4 = *reinterpret_cast<const float4*>(&W[(m0 + row) * 256 + k0 + c4]);
            Ws[c4 + 0][row] = w4.x; Ws[c4 + 1][row] = w4.y;
            Ws[c4 + 2][row] = w4.z; Ws[c4 + 3][row] = w4.w;
        }
        {
            int kk = t >> 4, n4 = (t & 15) * 4;
            float4 b4 = *reinterpret_cast<const float4*>(&in[(k0 + kk) * 256 + n0 + n4]);
            if (XFORM) {
                b4.x = 2.f * b4.x - 1.f; b4.y = 2.f * b4.y - 1.f;
                b4.z = 2.f * b4.z - 1.f; b4.w = 2.f * b4.w - 1.f;
            }
            *reinterpret_cast<float4*>(&Bs[kk][n4]) = b4;
        }
        __syncthreads();
        #pragma unroll
        for (int kk = 0; kk < 16; kk++) {
            float a[4], b[4];
            *reinterpret_cast<float4*>(a) = *reinterpret_cast<float4*>(&Ws[kk][ty * 4]);
            *reinterpret_cast<float4*>(b) = *reinterpret_cast<float4*>(&Bs[kk][tx * 4]);
            #pragma unroll
            for (int i = 0; i < 4; i++)
                #pragma unroll
                for (int j = 0; j < 4; j++)
                    acc[i][j] += a[i] * b[j];
        }
        __syncthreads();
    }
    #pragma unroll
    for (int i = 0; i < 4; i++) {
        int m = m0 + ty * 4 + i;
        float bm = bias[m];
        float4 o;
        o.x = acc[i][0] + bm; o.y = acc[i][1] + bm;
        o.z = acc[i][2] + bm; o.w = acc[i][3] + bm;
        *reinterpret_cast<float4*>(&out[m * 256 + n0 + tx * 4]) = o;
    }
}

__global__ void k_zsq(const float* __restrict__ z) {
    int img = blockIdx.x, hw = threadIdx.x;
    const float* p = z + (size_t)img * 65536 + hw;
    float s = 0.f;
    #pragma unroll 8
    for (int e = 0; e < 256; e++) { float v = p[e * 256]; s += v * v; }
    g_zsq[img * 256 + hw] = s;
}

// ---------------------------------------------------------------------------
// bf16 mma.sync distance-score GEMM + per-pixel serial prune.
// CTA: 128 pixels x 4096 codes. Warp w owns pixel rows w*16..w*16+15 (full
// 128-code tiles). Score s = dot_bf16(z,c) - csq/2; ring of last 16 codes
// with s > runmax - MARGIN; cnt>16 => rescore does full scan (sound).
// SMEM: A 64KB | B0 16KB | B1 16KB | stage 8x2112 | csq_s 512B  = 113.0KB
// ---------------------------------------------------------------------------
#define AOFF      0
#define B0OFF     65536
#define B1OFF     81920
#define STGOFF    98304
#define CSQOFF    115200
#define SMEM_DIST 115712
#define MARGIN    2.5e-5f

__global__ void __launch_bounds__(256, 2) k_dist_mma(const float* __restrict__ z) {
    extern __shared__ char smem[];
    const uint32_t sb = smem_u32(smem);
    const int t = threadIdx.x;
    const int wid = t >> 5, lane = t & 31;
    const int n_base = blockIdx.x * 128;

    // ---------------- A build: z (fp32 [e][pix]) -> bf16 swizzled [pix][e] ----
    {
        const float* zsrc = z + (size_t)(n_base >> 8) * 65536 + (n_base & 255);
        float* scr = reinterpret_cast<float*>(smem + B0OFF);   // 32e x 128pix fp32
        for (int kb = 0; kb < 8; kb++) {
            int e_l = t >> 3;
            int pg = (t & 7) * 16;
            const float4* s4 = reinterpret_cast<const float4*>(zsrc + (kb * 32 + e_l) * 256 + pg);
            float4 v0 = s4[0], v1 = s4[1], v2 = s4[2], v3 = s4[3];
            float4* d4 = reinterpret_cast<float4*>(scr + e_l * 128 + pg);
            d4[0] = v0; d4[1] = v1; d4[2] = v2; d4[3] = v3;
            __syncthreads();
            int pix = t & 127, half = t >> 7;
            #pragma unroll
            for (int jj = 0; jj < 8; jj++) {
                int el0 = (half * 8 + jj) * 2;
                float a = scr[el0 * 128 + pix], b = scr[(el0 + 1) * 128 + pix];
                uint32_t u;
                asm("cvt.rn.bf16x2.f32 %0, %1, %2;" : "=r"(u) : "f"(b), "f"(a));
                int eg = kb * 32 + el0;
                uint32_t unit = (uint32_t)(eg >> 3) ^ (uint32_t)(pix & 7);
                uint32_t addr = sb + AOFF + (uint32_t)pix * 512 + unit * 16 + (eg & 7) * 2;
                asm volatile("st.shared.b32 [%0], %1;" :: "r"(addr), "r"(u) : "memory");
            }
            __syncthreads();
        }
    }

    // per-lane precomputed pieces
    const int wbase = wid * 16;
    const int arow = wbase + (lane & 7) + ((lane >> 3) & 1) * 8;   // A row for ldmatrix
    const uint32_t aswz = (uint32_t)(arow & 7);
    const uint32_t abase = sb + AOFF + (uint32_t)arow * 512;
    const int ag2 = lane >> 4;                                     // klo/khi
    const int brp = ((lane >> 4) & 1) * 8 + (lane & 7);            // B row within nf-pair
    const int bg1 = (lane >> 3) & 1;                               // klo/khi
    float* stg = reinterpret_cast<float*>(smem + STGOFF + wid * 2112);
    float* csq_s = reinterpret_cast<float*>(smem + CSQOFF);

    float acc[16][4];
    #pragma unroll
    for (int i = 0; i < 16; i++)
        #pragma unroll
        for (int j = 0; j < 4; j++) acc[i][j] = 0.f;

    float runmax = -1e30f;
    int cnt = 0;
    uint32_t r0 = 0, r1 = 0, r2 = 0, r3 = 0, r4 = 0, r5 = 0, r6 = 0, r7 = 0;

    // B chunk loader: 128 codes x 64 emb of tile nt, k-chunk kc -> buf
    auto loadB = [&](int nt, int kc, uint32_t boff) {
        int code = t >> 1;
        const char* src = reinterpret_cast<const char*>(
            g_cbh + ((size_t)(nt * 128 + code)) * 256 + kc * 64 + (t & 1) * 32);
        uint32_t drow = sb + boff + (uint32_t)code * 128;
        uint32_t sw = (uint32_t)(code & 7);
        #pragma unroll
        for (int i = 0; i < 4; i++) {
            uint32_t u = (uint32_t)((t & 1) * 4 + i);
            CPA16(drow + (u ^ sw) * 16, src + i * 16);
        }
    };

    loadB(0, 0, B0OFF);
    CP_COMMIT();

    for (int c = 0; c < 128; ++c) {
        const int nt = c >> 2, kc = c & 3;
        if (c < 127) { loadB((c + 1) >> 2, (c + 1) & 3, ((c + 1) & 1) ? B1OFF : B0OFF); CP_COMMIT(); }
        if (kc == 0 && t < 128) csq_s[t] = g_csqh[nt * 128 + t];
        if (c < 127) asm volatile("cp.async.wait_group 1;" ::: "memory");
        else         asm volatile("cp.async.wait_group 0;" ::: "memory");
        __syncthreads();

        const uint32_t bbuf = sb + ((c & 1) ? B1OFF : B0OFF);
        #pragma unroll
        for (int ks = 0; ks < 4; ks++) {
            uint32_t a0, a1, a2, a3;
            {
                uint32_t unit = (uint32_t)(kc * 8 + 2 * ks + ag2) ^ aswz;
                LDM4(a0, a1, a2, a3, abase + unit * 16);
            }
            #pragma unroll
            for (int p = 0; p < 8; p++) {
                int brow = p * 16 + brp;
                uint32_t unit = (uint32_t)(2 * ks + bg1) ^ (uint32_t)(brow & 7);
                uint32_t b0, b1, b2, b3;
                LDM4(b0, b1, b2, b3, bbuf + (uint32_t)brow * 128 + unit * 16);
                MMA16816(acc[2 * p],     a0, a1, a2, a3, b0, b1);
                MMA16816(acc[2 * p + 1], a0, a1, a2, a3, b2, b3);
            }
        }

        if (kc == 3) {
            // epilogue: serial per-pixel prune (warm-up pass for tile 0)
            for (int pass = (nt == 0 ? 0 : 1); pass < 2; ++pass) {
                for (int q = 0; q < 4; ++q) {
                    #pragma unroll
                    for (int nfl = 0; nfl < 4; ++nfl) {
                        int nf = q * 4 + nfl;
                        int rr = lane >> 2;
                        int cc = nfl * 8 + 2 * (lane & 3);
                        stg[rr * 33 + cc]            = acc[nf][0];
                        stg[rr * 33 + cc + 1]        = acc[nf][1];
                        stg[(rr + 8) * 33 + cc]      = acc[nf][2];
                        stg[(rr + 8) * 33 + cc + 1]  = acc[nf][3];
                    }
                    __syncwarp();
                    if (lane < 16) {
                        const float* row = stg + lane * 33;
                        const float* cq = csq_s + q * 32;
                        #pragma unroll 4
                        for (int j = 0; j < 32; ++j) {
                            float s = row[j] - cq[j];
                            if (pass == 0) {
                                runmax = fmaxf(runmax, s);
                            } else if (s > runmax - MARGIN) {
                                r7 = (r7 << 16) | (r6 >> 16); r6 = (r6 << 16) | (r5 >> 16);
                                r5 = (r5 << 16) | (r4 >> 16); r4 = (r4 << 16) | (r3 >> 16);
                                r3 = (r3 << 16) | (r2 >> 16); r2 = (r2 << 16) | (r1 >> 16);
                                r1 = (r1 << 16) | (r0 >> 16);
                                r0 = (r0 << 16) | (uint32_t)(nt * 128 + q * 32 + j);
                                cnt++;
                                runmax = fmaxf(runmax, s);
                            }
                        }
                    }
                    __syncwarp();
                }
            }
            #pragma unroll
            for (int i = 0; i < 16; i++)
                #pragma unroll
                for (int j = 0; j < 4; j++) acc[i][j] = 0.f;
        }
        __syncthreads();
    }

    if (lane < 16) {
        int pix = n_base + wbase + lane;
        g_cnt[pix] = cnt;
        uint32_t* cp = reinterpret_cast<uint32_t*>(g_cand[pix]);
        cp[0] = r0; cp[1] = r1; cp[2] = r2; cp[3] = r3;
        cp[4] = r4; cp[5] = r5; cp[6] = r6; cp[7] = r7;
    }
}

// ---------------------------------------------------------------------------
// Exact fp32 rescore. Block = 128 pixels; z staged transposed in smem.
// ---------------------------------------------------------------------------
#define SMEM_RESC (128 * 264 * 4)

__global__ void __launch_bounds__(256) k_rescore(
    const float* __restrict__ cb, const float* __restrict__ z,
    float* __restrict__ tok_out)
{
    extern __shared__ float zs[];     // [128][264]
    const int t = threadIdx.x;
    const int wid = t >> 5, lane = t & 31;
    const int n_base = blockIdx.x * 128;
    const float* zsrc = z + (size_t)(n_base >> 8) * 65536 + (n_base & 255);

    for (int kb = 0; kb < 8; kb++) {
        int e = kb * 32 + (t >> 3);
        int pg = (t & 7) * 16;
        const float4* s4 = reinterpret_cast<const float4*>(zsrc + e * 256 + pg);
        float4 v[4] = { s4[0], s4[1], s4[2], s4[3] };
        const float* vf = reinterpret_cast<const float*>(v);
        #pragma unroll
        for (int j = 0; j < 16; j++) zs[(pg + j) * 264 + e] = vf[j];
    }
    __syncthreads();

    for (int it = 0; it < 16; ++it) {
        const int pl = wid * 16 + it;
        const int pix = n_base + pl;
        const int cnt = g_cnt[pix];
        const float zq2 = g_zsq[pix];
        const float* zrow = zs + pl * 264;
        unsigned long long best = ~0ull;

        if (cnt <= 16) {
            for (int ci = 0; ci < cnt; ++ci) {
                int v = g_cand[pix][ci];
                const float* crow = cb + (size_t)v * 256;
                float part = 0.f;
                #pragma unroll
                for (int j = 0; j < 8; j++)
                    part = fmaf(zrow[lane * 8 + j], crow[lane * 8 + j], part);
                #pragma unroll
                for (int o = 16; o; o >>= 1)
                    part += __shfl_xor_sync(0xFFFFFFFFu, part, o);
                float d = (zq2 + g_csq[v]) - 2.0f * part;
                unsigned long long key = ((unsigned long long)f2ord(d) << 32) | (unsigned int)v;
                if (key < best) best = key;
            }
        } else {
            for (int v = 0; v < VOCAB; ++v) {
                const float* crow = cb + (size_t)v * 256;
                float part = 0.f;
                #pragma unroll
                for (int j = 0; j < 8; j++)
                    part = fmaf(zrow[lane * 8 + j], crow[lane * 8 + j], part);
                #pragma unroll
                for (int o = 16; o; o >>= 1)
                    part += __shfl_xor_sync(0xFFFFFFFFu, part, o);
                float d = (zq2 + g_csq[v]) - 2.0f * part;
                unsigned long long key = ((unsigned long long)f2ord(d) << 32) | (unsigned int)v;
                if (key < best) best = key;
            }
        }
        if (lane == 0) {
            int tok = (int)(best & 0xFFFFFFFFull);
            g_tok[pix] = tok;
            tok_out[pix] = (float)tok;
        }
    }
}

__global__ void k_zq(const float* __restrict__ cb, float* __restrict__ zq) {
    unsigned int g = blockIdx.x * 256 + threadIdx.x;
    int hw = g & 255, e = (g >> 8) & 255, img = g >> 16;
    zq[g] = cb[(size_t)g_tok[img * 256 + hw] * 256 + e];
}

// ---------------------------------------------------------------------------
extern "C" void kernel_launch(void* const* d_in, const int* in_sizes, int n_in,
                              void* d_out, int out_size) {
    const float* x      = (const float*)d_in[0];
    const float* cb     = (const float*)d_in[1];
    const float* pre_w  = (const float*)d_in[2];
    const float* pre_b  = (const float*)d_in[3];
    const float* post_w = (const float*)d_in[4];
    const float* post_b = (const float*)d_in[5];

    float* out   = (float*)d_out;
    float* zbuf  = out;
    float* zq    = out + 8388608;
    float* recon = out + 16777216;
    float* toks  = out + 25165824;

    static bool attr_done = false;
    if (!attr_done) {
        cudaFuncSetAttribute(k_dist_mma, cudaFuncAttributeMaxDynamicSharedMemorySize, SMEM_DIST);
        cudaFuncSetAttribute(k_rescore,  cudaFuncAttributeMaxDynamicSharedMemorySize, SMEM_RESC);
        attr_done = true;
    }

    k_init<<<1024, 128>>>(cb);
    k_cbh<<<4096, 256>>>(cb);
    k_gemm256<true><<<dim3(4, 4, IMGS), 256>>>(pre_w, pre_b, x, zbuf);
    k_zsq<<<IMGS, 256>>>(zbuf);
    k_dist_mma<<<NPIX / 128, 256, SMEM_DIST>>>(zbuf);
    k_rescore<<<NPIX / 128, 256, SMEM_RESC>>>(cb, zbuf, toks);
    k_zq<<<8388608 / 256, 256>>>(cb, zq);
    k_gemm256<false><<<dim3(4, 4, IMGS), 256>>>(post_w, post_b, zq, recon);
}